// round 7
// baseline (speedup 1.0000x reference)
#include <cuda_runtime.h>
#include <cuda_bf16.h>
#include <math.h>
#include <math_constants.h>
#include <cstdint>

#define BATCH 16
#define TLEN  2048
#define HDIM  64
#define DDIM  512
#define MTOT  (BATCH * TLEN)

// Precomputed per-token 4-vectors (E,px,py,pz); entries >= len padded (-1e30,0,0,0).
__device__ float4 g_P[(size_t)MTOT];
__device__ int    g_len[BATCH];
// h split into bf16 hi/lo, row-major [M][64].
__device__ __nv_bfloat16 g_hh[(size_t)MTOT * HDIM];
__device__ __nv_bfloat16 g_hl[(size_t)MTOT * HDIM];
// W2 split into bf16 hi/lo, [N][K] layout.
__device__ __nv_bfloat16 g_whi[DDIM * HDIM];
__device__ __nv_bfloat16 g_wlo[DDIM * HDIM];

__device__ __forceinline__ float mass_from_sum(float sE, float sx, float sy, float sz) {
    float s2 = sx * sx + sy * sy + sz * sz;
    float m2 = sE * sE - s2;
    m2 = fmaxf(m2, 0.0f);
    return sqrtf(m2 + 1e-8f);
}

// ---- packed fp32x2 helpers ----
__device__ __forceinline__ unsigned long long pk2(float x, float y) {
    unsigned long long r;
    asm("mov.b64 %0, {%1, %2};" : "=l"(r) : "f"(x), "f"(y));
    return r;
}
__device__ __forceinline__ void upk2(unsigned long long a, float& x, float& y) {
    asm("mov.b64 {%0, %1}, %2;" : "=f"(x), "=f"(y) : "l"(a));
}
__device__ __forceinline__ void ffma2(unsigned long long& acc, unsigned long long a, unsigned long long b) {
    asm("fma.rn.f32x2 %0, %1, %2, %0;" : "+l"(acc) : "l"(a), "l"(b));
}
__device__ __forceinline__ float dot2(unsigned long long ql, unsigned long long qh, ulonglong2 p) {
    unsigned long long acc = 0ull;
    ffma2(acc, ql, p.x);
    ffma2(acc, qh, p.y);
    float lo, hi;
    upk2(acc, lo, hi);
    return lo + hi;
}

// ---------------------------------------------------------------------------
// Prep kernel. Blocks 0..15: P = (E,px,py,pz) from tokens, length from mask,
// pad tail with (-1e30,0,0,0). Blocks 16..17: W2 bf16 hi/lo split.
// ---------------------------------------------------------------------------
__global__ __launch_bounds__(256) void prep_kernel(
    const float* __restrict__ tok,     // [B,T,4]
    const void*  __restrict__ maskp,   // [B,T] bool — dtype probed (u8 / 32-bit)
    const float* __restrict__ W2)      // [64,512]
{
    const int b   = blockIdx.x;
    const int tid = threadIdx.x;

    if (b < BATCH) {
        __shared__ int red[8];
        __shared__ int sL;
        const unsigned int w0 = *(const unsigned int*)maskp;
        const bool byte_mode = (w0 == 0x01010101u) || (w0 == 0xFFFFFFFFu);

        int cnt = 0;
        #pragma unroll
        for (int i = 0; i < 8; i++) {
            int s = tid + 256 * i;
            float4 c = ((const float4*)tok)[b * TLEN + s];
            float E = c.x, Pt = c.y, eta = c.z, phi = c.w;
            float sphi, cphi;
            sincosf(phi, &sphi, &cphi);
            float px = Pt * cphi;
            float py = Pt * sphi;
            eta = fminf(fmaxf(eta, -20.0f), 20.0f);
            float pz = Pt * sinhf(eta);
            g_P[(size_t)b * TLEN + s] = make_float4(E, px, py, pz);
            if (byte_mode)
                cnt += (((const unsigned char*)maskp)[b * TLEN + s] != 0) ? 1 : 0;
            else
                cnt += (((const unsigned int*)maskp)[b * TLEN + s] != 0u) ? 1 : 0;
        }
        #pragma unroll
        for (int o = 16; o > 0; o >>= 1) cnt += __shfl_down_sync(0xffffffffu, cnt, o);
        if ((tid & 31) == 0) red[tid >> 5] = cnt;
        __syncthreads();
        if (tid == 0) {
            int L = 0;
            #pragma unroll
            for (int i = 0; i < 8; i++) L += red[i];
            sL = L;
            g_len[b] = L;
        }
        __syncthreads();
        const int L = sL;
        // pad invalid candidates: dot with any query (E>=1) is <= -1e30 -> never selected
        for (int s = L + tid; s < TLEN; s += 256)
            g_P[(size_t)b * TLEN + s] = make_float4(-1e30f, 0.0f, 0.0f, 0.0f);
    } else {
        const int half = b - BATCH;
        for (int i = tid; i < 16384; i += 256) {
            int idx = half * 16384 + i;
            int n = idx >> 6;
            int k = idx & 63;
            float w = W2[k * DDIM + n];
            __nv_bfloat16 hi = __float2bfloat16(w);
            float lo = w - __bfloat162float(hi);
            g_whi[idx] = hi;
            g_wlo[idx] = __float2bfloat16(lo);
        }
    }
}

// ---------------------------------------------------------------------------
// Kernel A: 2 lanes per token, pair-processed candidates (2 per iteration)
// with shared guard. Lane r scans pairs {4k+2r, 4k+2r+1} (ascending within
// lane -> strict-> cascade preserves lax.top_k tie order). Pairwise shuffle
// merge (value desc, index asc) -> global top-8 -> masses -> h=gelu(mass@W1+b1).
// Grid: (TLEN/64, BATCH), 128 threads (64 tokens per block).
// ---------------------------------------------------------------------------
__global__ __launch_bounds__(128) void mass_h_kernel(
    const float* __restrict__ W1,      // [3,64]
    const float* __restrict__ b1)      // [64]
{
    __shared__ float4 sP[TLEN];

    const int b   = blockIdx.y;
    const int tid = threadIdx.x;

    #pragma unroll
    for (int i = 0; i < 16; i++) {
        int s = tid + 128 * i;
        sP[s] = g_P[(size_t)b * TLEN + s];
    }
    const int L = g_len[b];
    __syncthreads();

    const int r = tid & 1;
    const int t = blockIdx.x * 64 + (tid >> 1);

    float mass0, mass1, mass2;

    if (t < L) {
        float4 q = sP[t];
        const unsigned long long ql = pk2(q.x, -q.y);
        const unsigned long long qh = pk2(-q.z, -q.w);

        float v[8];
        int   ix[8];
        #pragma unroll
        for (int j = 0; j < 8; j++) { v[j] = -CUDART_INF_F; ix[j] = 0x7fffffff; }

        const ulonglong2* sp2 = (const ulonglong2*)sP;

        #pragma unroll 4
        for (int s0 = 2 * r; s0 < L; s0 += 4) {
            ulonglong2 pa = sp2[s0];
            ulonglong2 pb = sp2[s0 + 1];
            float d0 = dot2(ql, qh, pa);
            float d1 = dot2(ql, qh, pb);
            if (fmaxf(d0, d1) > v[7]) {
                if (d0 > v[7]) {
                    float nv = d0; int ni = s0;
                    #pragma unroll
                    for (int j = 0; j < 8; j++) {
                        bool sw  = nv > v[j];
                        float hi = fmaxf(nv, v[j]);
                        float lo = fminf(nv, v[j]);
                        int hidx = sw ? ni    : ix[j];
                        int lidx = sw ? ix[j] : ni;
                        v[j] = hi; ix[j] = hidx;
                        nv   = lo; ni    = lidx;
                    }
                }
                if (d1 > v[7]) {
                    float nv = d1; int ni = s0 + 1;
                    #pragma unroll
                    for (int j = 0; j < 8; j++) {
                        bool sw  = nv > v[j];
                        float hi = fmaxf(nv, v[j]);
                        float lo = fminf(nv, v[j]);
                        int hidx = sw ? ni    : ix[j];
                        int lidx = sw ? ix[j] : ni;
                        v[j] = hi; ix[j] = hidx;
                        nv   = lo; ni    = lidx;
                    }
                }
            }
        }

        // Merge the two sorted 8-lists: 8 rounds of pair-max (value desc, index asc).
        float sE = 0.f, sx = 0.f, sy = 0.f, sz = 0.f;
        mass0 = mass1 = mass2 = 0.f;
        #pragma unroll
        for (int j = 0; j < 8; j++) {
            float ov = __shfl_xor_sync(0xffffffffu, v[0],  1);
            int   oi = __shfl_xor_sync(0xffffffffu, ix[0], 1);
            bool take_other = (ov > v[0]) || (ov == v[0] && oi < ix[0]);
            int  wi  = take_other ? oi : ix[0];
            bool won = !take_other;
            #pragma unroll
            for (int u = 0; u < 7; u++) {
                v[u]  = won ? v[u + 1]  : v[u];
                ix[u] = won ? ix[u + 1] : ix[u];
            }
            if (won) { v[7] = -CUDART_INF_F; ix[7] = 0x7fffffff; }

            float4 p = sP[wi];
            sE += p.x; sx += p.y; sy += p.z; sz += p.w;
            if (j == 1) mass0 = mass_from_sum(sE, sx, sy, sz);
            if (j == 3) mass1 = mass_from_sum(sE, sx, sy, sz);
            if (j == 7) mass2 = mass_from_sum(sE, sx, sy, sz);
        }
    } else {
        float mm = sqrtf(1e-8f);  // m2 * 0 -> sqrt(1e-8), as the reference
        mass0 = mass1 = mass2 = mm;
    }

    // h = gelu(mass @ W1 + b1), stored as bf16 hi/lo split, row-major [m][c].
    const size_t m = (size_t)b * TLEN + t;
    #pragma unroll
    for (int cc = 0; cc < 32; cc += 2) {
        int c = r * 32 + cc;
        float g2[2];
        #pragma unroll
        for (int u = 0; u < 2; u++) {
            float x = fmaf(mass0, __ldg(&W1[c + u]),
                      fmaf(mass1, __ldg(&W1[HDIM + c + u]),
                      fmaf(mass2, __ldg(&W1[2 * HDIM + c + u]), __ldg(&b1[c + u]))));
            g2[u] = x * 0.5f * (1.0f + erff(x * 0.70710678118654752f));
        }
        __nv_bfloat16 h0 = __float2bfloat16(g2[0]);
        __nv_bfloat16 h1 = __float2bfloat16(g2[1]);
        __nv_bfloat16 l0 = __float2bfloat16(g2[0] - __bfloat162float(h0));
        __nv_bfloat16 l1 = __float2bfloat16(g2[1] - __bfloat162float(h1));
        *(__nv_bfloat162*)&g_hh[m * HDIM + c] = __nv_bfloat162(h0, h1);
        *(__nv_bfloat162*)&g_hl[m * HDIM + c] = __nv_bfloat162(l0, l1);
    }
}

// ---------------------------------------------------------------------------
// mma.sync GEMM: out[M,512] = (hh+hl)[M,64] @ (Whi+Wlo)^T + b2
// 3 bf16 products: Ah*Bh + Ah*Bl + Al*Bh (compensated, err ~3e-5).
// CTA: 128M x 128N, 256 threads (8 warps, warp = 32M x 64N), K=64.
// ---------------------------------------------------------------------------
#define SW128(o) ((o) ^ (((o) >> 3) & 0x70))
#define GSM_AH 0
#define GSM_AL 16384
#define GSM_BH 32768
#define GSM_BL 49152
#define GSM_TOT 65536

__device__ __forceinline__ uint32_t smem_u32(const void* p) {
    uint32_t a;
    asm("{ .reg .u64 t; cvta.to.shared.u64 t, %1; cvt.u32.u64 %0, t; }" : "=r"(a) : "l"(p));
    return a;
}
__device__ __forceinline__ void ldmx4(uint32_t* r, uint32_t addr) {
    asm volatile("ldmatrix.sync.aligned.m8n8.x4.shared.b16 {%0,%1,%2,%3}, [%4];"
        : "=r"(r[0]), "=r"(r[1]), "=r"(r[2]), "=r"(r[3]) : "r"(addr));
}
__device__ __forceinline__ void mma16816(float* c, const uint32_t* a, const uint32_t* b) {
    asm volatile("mma.sync.aligned.m16n8k16.row.col.f32.bf16.bf16.f32 "
        "{%0,%1,%2,%3}, {%4,%5,%6,%7}, {%8,%9}, {%0,%1,%2,%3};"
        : "+f"(c[0]), "+f"(c[1]), "+f"(c[2]), "+f"(c[3])
        : "r"(a[0]), "r"(a[1]), "r"(a[2]), "r"(a[3]), "r"(b[0]), "r"(b[1]));
}

__global__ __launch_bounds__(256) void gemm_mma_kernel(
    const float* __restrict__ b2,   // [512]
    float* __restrict__ out)        // [M,512]
{
    extern __shared__ __align__(1024) char smem[];
    const uint32_t sbase = smem_u32(smem);
    const int tid  = threadIdx.x;
    const int wid  = tid >> 5;
    const int lane = tid & 31;
    const int m0   = blockIdx.x * 128;
    const int n0   = blockIdx.y * 128;

    #pragma unroll
    for (int i = 0; i < 4; i++) {
        int f  = tid + 256 * i;
        int rr = f >> 3;
        int qq = f & 7;
        uint32_t off = SW128((uint32_t)(rr * 128 + qq * 16));
        *(uint4*)(smem + GSM_AH + off) = *(const uint4*)(g_hh  + (size_t)(m0 + rr) * HDIM + qq * 8);
        *(uint4*)(smem + GSM_AL + off) = *(const uint4*)(g_hl  + (size_t)(m0 + rr) * HDIM + qq * 8);
        *(uint4*)(smem + GSM_BH + off) = *(const uint4*)(g_whi + (size_t)(n0 + rr) * HDIM + qq * 8);
        *(uint4*)(smem + GSM_BL + off) = *(const uint4*)(g_wlo + (size_t)(n0 + rr) * HDIM + qq * 8);
    }
    __syncthreads();

    const int wm = (wid & 3) * 32;
    const int wn = (wid >> 2) * 64;

    float acc[2][8][4];
    #pragma unroll
    for (int mt = 0; mt < 2; mt++)
        #pragma unroll
        for (int nt = 0; nt < 8; nt++)
            #pragma unroll
            for (int u = 0; u < 4; u++) acc[mt][nt][u] = 0.0f;

    const int a_row_l = lane & 15;
    const int a_kb_l  = (lane >> 4) * 16;
    const int b_n_l   = ((lane >> 4) << 3) + (lane & 7);
    const int b_kb_l  = ((lane >> 3) & 1) * 16;

    #pragma unroll
    for (int ks = 0; ks < 4; ks++) {
        uint32_t ah[2][4], al[2][4];
        #pragma unroll
        for (int mt = 0; mt < 2; mt++) {
            uint32_t off = SW128((uint32_t)((wm + mt * 16 + a_row_l) * 128 + ks * 32 + a_kb_l));
            ldmx4(ah[mt], sbase + GSM_AH + off);
            ldmx4(al[mt], sbase + GSM_AL + off);
        }
        #pragma unroll
        for (int np = 0; np < 4; np++) {
            uint32_t bh[4], bl[4];
            uint32_t off = SW128((uint32_t)((wn + np * 16 + b_n_l) * 128 + ks * 32 + b_kb_l));
            ldmx4(bh, sbase + GSM_BH + off);
            ldmx4(bl, sbase + GSM_BL + off);
            #pragma unroll
            for (int mt = 0; mt < 2; mt++) {
                mma16816(acc[mt][2 * np],     ah[mt], bh);
                mma16816(acc[mt][2 * np],     ah[mt], bl);
                mma16816(acc[mt][2 * np],     al[mt], bh);
                mma16816(acc[mt][2 * np + 1], ah[mt], bh + 2);
                mma16816(acc[mt][2 * np + 1], ah[mt], bl + 2);
                mma16816(acc[mt][2 * np + 1], al[mt], bh + 2);
            }
        }
    }

    const int er = lane >> 2;
    const int ec = (lane & 3) * 2;
    #pragma unroll
    for (int mt = 0; mt < 2; mt++) {
        #pragma unroll
        for (int nt = 0; nt < 8; nt++) {
            int n = n0 + wn + nt * 8 + ec;
            float bx = __ldg(&b2[n]);
            float by = __ldg(&b2[n + 1]);
            int row0 = m0 + wm + mt * 16 + er;
            float2 o0 = make_float2(acc[mt][nt][0] + bx, acc[mt][nt][1] + by);
            float2 o1 = make_float2(acc[mt][nt][2] + bx, acc[mt][nt][3] + by);
            *(float2*)&out[(size_t)row0 * DDIM + n]       = o0;
            *(float2*)&out[(size_t)(row0 + 8) * DDIM + n] = o1;
        }
    }
}

// ---------------------------------------------------------------------------
extern "C" void kernel_launch(void* const* d_in, const int* in_sizes, int n_in,
                              void* d_out, int out_size) {
    const float* tok  = (const float*)d_in[0];   // [16,2048,4]
    const void*  mask = (const void*)d_in[1];    // [16,2048] bool (dtype probed)
    const float* W1   = (const float*)d_in[2];   // [3,64]
    const float* b1   = (const float*)d_in[3];   // [64]
    const float* W2   = (const float*)d_in[4];   // [64,512]
    const float* b2   = (const float*)d_in[5];   // [512]
    float*       out  = (float*)d_out;           // [16,2048,512]

    static bool attr_done = false;
    if (!attr_done) {
        cudaFuncSetAttribute(gemm_mma_kernel, cudaFuncAttributeMaxDynamicSharedMemorySize, GSM_TOT);
        attr_done = true;
    }

    prep_kernel<<<BATCH + 2, 256>>>(tok, mask, W2);

    dim3 gA(TLEN / 64, BATCH);
    mass_h_kernel<<<gA, 128>>>(W1, b1);

    dim3 gG(MTOT / 128, DDIM / 128);
    gemm_mma_kernel<<<gG, 256, GSM_TOT>>>(b2, out);
}